// round 12
// baseline (speedup 1.0000x reference)
#include <cuda_runtime.h>
#include <cuda_fp16.h>
#include <math_constants.h>
#include <cstdint>

// Problem constants
#define BATCH 2
#define SEQ   2048
#define CH    1024
#define HEADS 16
#define DH    64
#define MROWS (BATCH*SEQ)   // 4096

// ---------------------------------------------------------------------------
// Device scratch
// ---------------------------------------------------------------------------
__device__ float  g_qkv[(size_t)MROWS * 3 * CH];
__device__ __half g_A[(size_t)MROWS * CH];
__device__ __half g_Vh[(size_t)MROWS * CH];    // fp16 copy of V (from GEMM1 epilogue)
__device__ __half g_BQ[(size_t)(3*CH) * CH];   // W_qkv^T fp16
__device__ __half g_BP[(size_t)CH * CH];       // W_proj^T fp16

// ---------------------------------------------------------------------------
// Helpers
// ---------------------------------------------------------------------------
__device__ __forceinline__ uint32_t smem_u32(const void* p) {
    uint32_t a;
    asm("{ .reg .u64 t; cvta.to.shared.u64 t, %1; cvt.u32.u64 %0, t; }"
        : "=r"(a) : "l"(p));
    return a;
}

#define SWZ128(o) ((o) ^ (((o) >> 3) & 0x70))

#define CP_ASYNC16(dst_u32, src_ptr) \
    asm volatile("cp.async.cg.shared.global [%0], [%1], 16;\n" \
                 :: "r"(dst_u32), "l"(src_ptr))
#define CP_COMMIT() asm volatile("cp.async.commit_group;\n" ::: "memory")
#define CP_WAIT0()  asm volatile("cp.async.wait_group 0;\n" ::: "memory")
#define CP_WAIT1()  asm volatile("cp.async.wait_group 1;\n" ::: "memory")

#define LDSM_X4(r0, r1, r2, r3, addr) \
    asm volatile("ldmatrix.sync.aligned.m8n8.x4.shared.b16 {%0,%1,%2,%3}, [%4];" \
                 : "=r"(r0), "=r"(r1), "=r"(r2), "=r"(r3) : "r"(addr))
// fp16 MMA, f32 accumulate
#define MMA16816(d, a0, a1, a2, a3, b0, b1) \
    asm volatile("mma.sync.aligned.m16n8k16.row.col.f32.f16.f16.f32 " \
                 "{%0,%1,%2,%3},{%4,%5,%6,%7},{%8,%9},{%0,%1,%2,%3};" \
                 : "+f"((d)[0]), "+f"((d)[1]), "+f"((d)[2]), "+f"((d)[3]) \
                 : "r"(a0), "r"(a1), "r"(a2), "r"(a3), "r"(b0), "r"(b1))

// ---------------------------------------------------------------------------
// fp16 GEMM: C[M,N] = A[M,K] @ B[N,K]^T + bias
// CTA 128x128, KC=64, 3-stage cp.async pipeline, ONE barrier per chunk,
// TWO CTAs PER SM. 8 warps 2(M)x4(N), 64x32 warp tiles.
// Stage: A 16KB | B 16KB = 32KB; 3 stages = 96KB/CTA -> 2 CTAs = 195KB/SM.
// Optional fp16 side-output of columns >= vcol0 (V copy for attention).
// ---------------------------------------------------------------------------
#define KC 64
#define STAGE_BYTES 32768
#define NSTAGE 3
#define GEMM_SMEM (1024 + NSTAGE * STAGE_BYTES)   // 99328 B

__device__ __forceinline__ void load_chunk_tiles(
    const __half* __restrict__ A, const __half* __restrict__ B,
    int K, int m0, int n0, int c, uint32_t st, int tid)
{
    #pragma unroll
    for (int t = 0; t < 4; t++) {
        int idx = t * 256 + tid;     // 0..1023
        int row = idx >> 3;          // 0..127
        int col = idx & 7;           // 16B chunk
        uint32_t off = SWZ128(row * 128 + col * 16);
        size_t ga = (size_t)(m0 + row) * K + c * KC + col * 8;
        size_t gb = (size_t)(n0 + row) * K + c * KC + col * 8;
        CP_ASYNC16(st + off,         A + ga);
        CP_ASYNC16(st + 16384 + off, B + gb);
    }
}

__global__ __launch_bounds__(256, 2)
void gemm_fp16_kernel(const __half* __restrict__ A,
                      const __half* __restrict__ B,
                      const float* __restrict__ bias,
                      float* __restrict__ C,
                      __half* __restrict__ Vh,   // nullable; fp16 copy of cols >= vcol0
                      int vcol0,
                      int N, int K)
{
    extern __shared__ char smem[];
    const uint32_t sb = smem_u32(smem);
    const uint32_t tiles = (sb + 1023) & ~1023u;
    const int tid  = threadIdx.x;
    const int wid  = tid >> 5;
    const int lane = tid & 31;
    const int m0 = blockIdx.y * 128;
    const int n0 = blockIdx.x * 128;
    const int NCHUNK = K / KC;

    const int warpM = wid >> 2;        // 0..1
    const int warpN = wid & 3;         // 0..3

    float acc[4][4][4];
    #pragma unroll
    for (int mt = 0; mt < 4; mt++)
        #pragma unroll
        for (int nt = 0; nt < 4; nt++)
            #pragma unroll
            for (int e = 0; e < 4; e++) acc[mt][nt][e] = 0.0f;

    // A ldmatrix.x4 (m16 x k16)
    const int aRowBase  = warpM * 64 + (lane & 15);
    const int aByteSel  = (lane >> 4) * 16;
    // B ldmatrix.x4 (two n8 tiles x k16) — layout verified R6-R11
    const int bRowSel   = warpN * 32 + (lane & 7) + ((lane >> 4) & 1) * 8;
    const int bByteSel  = ((lane >> 3) & 1) * 16;

    load_chunk_tiles(A, B, K, m0, n0, 0, tiles + 0 * STAGE_BYTES, tid);
    CP_COMMIT();
    load_chunk_tiles(A, B, K, m0, n0, 1, tiles + 1 * STAGE_BYTES, tid);
    CP_COMMIT();

    for (int c = 0; c < NCHUNK; ++c) {
        if (c < NCHUNK - 1) { CP_WAIT1(); } else { CP_WAIT0(); }
        __syncthreads();   // chunk c resident; all warps done reading stage (c+2)%3

        if (c + 2 < NCHUNK) {
            load_chunk_tiles(A, B, K, m0, n0, c + 2,
                             tiles + ((c + 2) % NSTAGE) * STAGE_BYTES, tid);
            CP_COMMIT();
        }

        const uint32_t st = tiles + (c % NSTAGE) * STAGE_BYTES;
        const uint32_t aB = st;
        const uint32_t bB = st + 16384;

        #pragma unroll
        for (int kk = 0; kk < 4; kk++) {
            uint32_t fa[4][4], fb[2][4];
            #pragma unroll
            for (int mt = 0; mt < 4; mt++) {
                uint32_t aoff = SWZ128((uint32_t)((aRowBase + mt * 16) * 128 + kk * 32 + aByteSel));
                LDSM_X4(fa[mt][0], fa[mt][1], fa[mt][2], fa[mt][3], aB + aoff);
            }
            #pragma unroll
            for (int p = 0; p < 2; p++) {
                uint32_t boff = SWZ128((uint32_t)((bRowSel + p * 16) * 128 + kk * 32 + bByteSel));
                LDSM_X4(fb[p][0], fb[p][1], fb[p][2], fb[p][3], bB + boff);
            }
            #pragma unroll
            for (int mt = 0; mt < 4; mt++)
                #pragma unroll
                for (int nt = 0; nt < 4; nt++)
                    MMA16816(acc[mt][nt],
                             fa[mt][0], fa[mt][1], fa[mt][2], fa[mt][3],
                             fb[nt >> 1][(nt & 1) * 2], fb[nt >> 1][(nt & 1) * 2 + 1]);
        }
    }

    // epilogue: bias + store (+ optional fp16 V copy)
    #pragma unroll
    for (int mt = 0; mt < 4; mt++) {
        int r0 = m0 + warpM * 64 + mt * 16 + (lane >> 2);
        #pragma unroll
        for (int nt = 0; nt < 4; nt++) {
            int c0 = n0 + warpN * 32 + nt * 8 + (lane & 3) * 2;
            float2 bv = *(const float2*)(bias + c0);
            float2 o0 = make_float2(acc[mt][nt][0] + bv.x, acc[mt][nt][1] + bv.y);
            float2 o1 = make_float2(acc[mt][nt][2] + bv.x, acc[mt][nt][3] + bv.y);
            *(float2*)(C + (size_t)r0 * N + c0)       = o0;
            *(float2*)(C + (size_t)(r0 + 8) * N + c0) = o1;
            if (Vh && c0 >= vcol0) {
                int cv = c0 - vcol0;
                *(__half2*)(Vh + (size_t)r0 * CH + cv) =
                    __halves2half2(__float2half_rn(o0.x), __float2half_rn(o0.y));
                *(__half2*)(Vh + (size_t)(r0 + 8) * CH + cv) =
                    __halves2half2(__float2half_rn(o1.x), __float2half_rn(o1.y));
            }
        }
    }
}

// ---------------------------------------------------------------------------
// Convert fp32 -> fp16
// ---------------------------------------------------------------------------
__global__ __launch_bounds__(256)
void conv_fp16_kernel(const float* __restrict__ in,
                      __half* __restrict__ o, int n4)
{
    int i = blockIdx.x * 256 + threadIdx.x;
    if (i >= n4) return;
    float4 v = ((const float4*)in)[i];
    ((__half2*)o)[2 * i + 0] = __halves2half2(__float2half_rn(v.x), __float2half_rn(v.y));
    ((__half2*)o)[2 * i + 1] = __halves2half2(__float2half_rn(v.z), __float2half_rn(v.w));
}

// ---------------------------------------------------------------------------
// Transpose: W[K,N] fp32 -> Wt[N,K] fp16
// ---------------------------------------------------------------------------
__global__ __launch_bounds__(256)
void conv_transpose_kernel(const float* __restrict__ W,
                           __half* __restrict__ o, int K, int N)
{
    __shared__ float tile[32][33];
    const int n0 = blockIdx.x * 32;
    const int k0 = blockIdx.y * 32;
    const int tx = threadIdx.x & 31;
    const int ty = threadIdx.x >> 5;

    #pragma unroll
    for (int j = ty; j < 32; j += 8)
        tile[j][tx] = W[(size_t)(k0 + j) * N + n0 + tx];
    __syncthreads();

    #pragma unroll
    for (int j = ty; j < 32; j += 8)
        o[(size_t)(n0 + j) * K + k0 + tx] = __float2half_rn(tile[tx][j]);
}

// ---------------------------------------------------------------------------
// Fenwick sparse attention — parallel-position formulation (verified R8-R11).
// Q,K read fp32 from qkv; V read fp16 (halves L2 traffic on the V pass).
// fp16 output (feeds GEMM2 A operand directly).
// ---------------------------------------------------------------------------
__global__ __launch_bounds__(256)
void fenwick_attn_kernel(const float* __restrict__ qkv,
                         const __half* __restrict__ Vh,
                         __half* __restrict__ outA)
{
    const int warp = threadIdx.x >> 5;
    const int lane = threadIdx.x & 31;
    const int t  = blockIdx.x * 8 + warp;
    const int bh = blockIdx.y;
    const int b = bh >> 4;
    const int h = bh & 15;

    const float scale = 0.125f;
    const size_t rowStride = 3 * CH;
    const float* base = qkv + (size_t)b * SEQ * rowStride;
    const __half* vbase = Vh + (size_t)b * SEQ * CH;

    bool active;
    int myPos;
    if (lane == 0) { myPos = t; active = true; }
    else           { int step = 1 << (lane - 1);
                     myPos = t - step;
                     active = (lane < 12) && (myPos >= 0); }
    if (!active) myPos = t;

    float s = -CUDART_INF_F;
    if (active) {
        const float4* qp4 = (const float4*)(base + (size_t)t * rowStride + h * DH);
        const float4* kp4 = (const float4*)(base + (size_t)myPos * rowStride + CH + h * DH);
        float d = 0.0f;
        #pragma unroll
        for (int i = 0; i < 16; i++) {
            float4 qv = qp4[i];
            float4 kv = kp4[i];
            d += qv.x * kv.x + qv.y * kv.y + qv.z * kv.z + qv.w * kv.w;
        }
        s = d * scale;
    }

    float m = s;
    #pragma unroll
    for (int off = 16; off; off >>= 1) m = fmaxf(m, __shfl_xor_sync(0xFFFFFFFFu, m, off));
    float e = active ? __expf(s - m) : 0.0f;
    float denom = e;
    #pragma unroll
    for (int off = 16; off; off >>= 1) denom += __shfl_xor_sync(0xFFFFFFFFu, denom, off);
    const float inv = 1.0f / denom;

    float o0 = 0.0f, o1 = 0.0f;
    #pragma unroll
    for (int j = 0; j < 12; j++) {
        float ej = __shfl_sync(0xFFFFFFFFu, e, j);
        int   pj = __shfl_sync(0xFFFFFFFFu, myPos, j);
        const __half* vp = vbase + (size_t)pj * CH + h * DH;
        o0 = fmaf(ej, __half2float(vp[lane]), o0);
        o1 = fmaf(ej, __half2float(vp[lane + 32]), o1);
    }
    o0 *= inv;
    o1 *= inv;

    const size_t o = ((size_t)b * SEQ + t) * CH + h * DH;
    outA[o + lane]      = __float2half_rn(o0);
    outA[o + lane + 32] = __float2half_rn(o1);
}

// ---------------------------------------------------------------------------
// Launch
// ---------------------------------------------------------------------------
extern "C" void kernel_launch(void* const* d_in, const int* in_sizes, int n_in,
                              void* d_out, int out_size)
{
    const float* x      = (const float*)d_in[0];
    const float* W_qkv  = (const float*)d_in[1];
    const float* b_qkv  = (const float*)d_in[2];
    const float* W_proj = (const float*)d_in[3];
    const float* b_proj = (const float*)d_in[4];
    float* out = (float*)d_out;

    float *qkv;
    __half *A, *Vh, *BQ, *BP;
    cudaGetSymbolAddress((void**)&qkv, g_qkv);
    cudaGetSymbolAddress((void**)&A,   g_A);
    cudaGetSymbolAddress((void**)&Vh,  g_Vh);
    cudaGetSymbolAddress((void**)&BQ,  g_BQ);
    cudaGetSymbolAddress((void**)&BP,  g_BP);

    cudaFuncSetAttribute(gemm_fp16_kernel,
                         cudaFuncAttributeMaxDynamicSharedMemorySize, GEMM_SMEM);

    conv_transpose_kernel<<<dim3(3 * CH / 32, CH / 32), 256>>>(W_qkv, BQ, CH, 3 * CH);
    conv_transpose_kernel<<<dim3(CH / 32, CH / 32), 256>>>(W_proj, BP, CH, CH);
    conv_fp16_kernel<<<(MROWS * CH / 4 + 255) / 256, 256>>>(x, A, MROWS * CH / 4);

    // GEMM1: [4096, 3072] = x @ W_qkv + b_qkv ; also emits fp16 copy of V cols
    gemm_fp16_kernel<<<dim3(3 * CH / 128, MROWS / 128), 256, GEMM_SMEM>>>(
        A, BQ, b_qkv, qkv, Vh, 2 * CH, 3 * CH, CH);

    // Attention (Q,K fp32; V fp16), fp16 output (overwrites A)
    fenwick_attn_kernel<<<dim3(SEQ / 8, BATCH * HEADS), 256>>>(qkv, Vh, A);

    // GEMM2: [4096, 1024] = att @ W_proj + b_proj (no side output)
    gemm_fp16_kernel<<<dim3(CH / 128, MROWS / 128), 256, GEMM_SMEM>>>(
        A, BP, b_proj, out, (__half*)nullptr, 0, CH, CH);
}

// round 13
// speedup vs baseline: 1.0199x; 1.0199x over previous
#include <cuda_runtime.h>
#include <cuda_fp16.h>
#include <math_constants.h>
#include <cstdint>

// Problem constants
#define BATCH 2
#define SEQ   2048
#define CH    1024
#define HEADS 16
#define DH    64
#define MROWS (BATCH*SEQ)   // 4096

// ---------------------------------------------------------------------------
// Device scratch
// ---------------------------------------------------------------------------
__device__ float  g_qkv[(size_t)MROWS * 3 * CH];
__device__ __half g_A[(size_t)MROWS * CH];
__device__ __half g_BQ[(size_t)(3*CH) * CH];   // W_qkv^T fp16
__device__ __half g_BP[(size_t)CH * CH];       // W_proj^T fp16

// ---------------------------------------------------------------------------
// Helpers
// ---------------------------------------------------------------------------
__device__ __forceinline__ uint32_t smem_u32(const void* p) {
    uint32_t a;
    asm("{ .reg .u64 t; cvta.to.shared.u64 t, %1; cvt.u32.u64 %0, t; }"
        : "=r"(a) : "l"(p));
    return a;
}

#define SWZ128(o) ((o) ^ (((o) >> 3) & 0x70))

#define CP_ASYNC16(dst_u32, src_ptr) \
    asm volatile("cp.async.cg.shared.global [%0], [%1], 16;\n" \
                 :: "r"(dst_u32), "l"(src_ptr))
#define CP_COMMIT() asm volatile("cp.async.commit_group;\n" ::: "memory")
#define CP_WAIT0()  asm volatile("cp.async.wait_group 0;\n" ::: "memory")
#define CP_WAIT1()  asm volatile("cp.async.wait_group 1;\n" ::: "memory")

#define LDSM_X4(r0, r1, r2, r3, addr) \
    asm volatile("ldmatrix.sync.aligned.m8n8.x4.shared.b16 {%0,%1,%2,%3}, [%4];" \
                 : "=r"(r0), "=r"(r1), "=r"(r2), "=r"(r3) : "r"(addr))
// fp16 MMA, f32 accumulate
#define MMA16816(d, a0, a1, a2, a3, b0, b1) \
    asm volatile("mma.sync.aligned.m16n8k16.row.col.f32.f16.f16.f32 " \
                 "{%0,%1,%2,%3},{%4,%5,%6,%7},{%8,%9},{%0,%1,%2,%3};" \
                 : "+f"((d)[0]), "+f"((d)[1]), "+f"((d)[2]), "+f"((d)[3]) \
                 : "r"(a0), "r"(a1), "r"(a2), "r"(a3), "r"(b0), "r"(b1))

// ---------------------------------------------------------------------------
// fp16 GEMM: C[M,N] = A[M,K] @ B[N,K]^T + bias
// CTA 128x128, KC=64, 3-stage cp.async pipeline, ONE barrier per chunk,
// TWO CTAs PER SM. 8 warps 2(M)x4(N), 64x32 warp tiles. No side outputs.
// Stage: A 16KB | B 16KB = 32KB; 3 stages = 96KB/CTA -> 2 CTAs = 195KB/SM.
// ---------------------------------------------------------------------------
#define KC 64
#define STAGE_BYTES 32768
#define NSTAGE 3
#define GEMM_SMEM (1024 + NSTAGE * STAGE_BYTES)   // 99328 B

__device__ __forceinline__ void load_chunk_tiles(
    const __half* __restrict__ A, const __half* __restrict__ B,
    int K, int m0, int n0, int c, uint32_t st, int tid)
{
    #pragma unroll
    for (int t = 0; t < 4; t++) {
        int idx = t * 256 + tid;     // 0..1023
        int row = idx >> 3;          // 0..127
        int col = idx & 7;           // 16B chunk
        uint32_t off = SWZ128(row * 128 + col * 16);
        size_t ga = (size_t)(m0 + row) * K + c * KC + col * 8;
        size_t gb = (size_t)(n0 + row) * K + c * KC + col * 8;
        CP_ASYNC16(st + off,         A + ga);
        CP_ASYNC16(st + 16384 + off, B + gb);
    }
}

__global__ __launch_bounds__(256, 2)
void gemm_fp16_kernel(const __half* __restrict__ A,
                      const __half* __restrict__ B,
                      const float* __restrict__ bias,
                      float* __restrict__ C,
                      int N, int K)
{
    extern __shared__ char smem[];
    const uint32_t sb = smem_u32(smem);
    const uint32_t tiles = (sb + 1023) & ~1023u;
    const int tid  = threadIdx.x;
    const int wid  = tid >> 5;
    const int lane = tid & 31;
    const int m0 = blockIdx.y * 128;
    const int n0 = blockIdx.x * 128;
    const int NCHUNK = K / KC;

    const int warpM = wid >> 2;        // 0..1
    const int warpN = wid & 3;         // 0..3

    float acc[4][4][4];
    #pragma unroll
    for (int mt = 0; mt < 4; mt++)
        #pragma unroll
        for (int nt = 0; nt < 4; nt++)
            #pragma unroll
            for (int e = 0; e < 4; e++) acc[mt][nt][e] = 0.0f;

    // A ldmatrix.x4 (m16 x k16)
    const int aRowBase  = warpM * 64 + (lane & 15);
    const int aByteSel  = (lane >> 4) * 16;
    // B ldmatrix.x4 (two n8 tiles x k16) — layout verified R6-R12
    const int bRowSel   = warpN * 32 + (lane & 7) + ((lane >> 4) & 1) * 8;
    const int bByteSel  = ((lane >> 3) & 1) * 16;

    load_chunk_tiles(A, B, K, m0, n0, 0, tiles + 0 * STAGE_BYTES, tid);
    CP_COMMIT();
    load_chunk_tiles(A, B, K, m0, n0, 1, tiles + 1 * STAGE_BYTES, tid);
    CP_COMMIT();

    for (int c = 0; c < NCHUNK; ++c) {
        if (c < NCHUNK - 1) { CP_WAIT1(); } else { CP_WAIT0(); }
        __syncthreads();   // chunk c resident; all warps done reading stage (c+2)%3

        if (c + 2 < NCHUNK) {
            load_chunk_tiles(A, B, K, m0, n0, c + 2,
                             tiles + ((c + 2) % NSTAGE) * STAGE_BYTES, tid);
            CP_COMMIT();
        }

        const uint32_t st = tiles + (c % NSTAGE) * STAGE_BYTES;
        const uint32_t aB = st;
        const uint32_t bB = st + 16384;

        #pragma unroll
        for (int kk = 0; kk < 4; kk++) {
            uint32_t fa[4][4], fb[2][4];
            #pragma unroll
            for (int mt = 0; mt < 4; mt++) {
                uint32_t aoff = SWZ128((uint32_t)((aRowBase + mt * 16) * 128 + kk * 32 + aByteSel));
                LDSM_X4(fa[mt][0], fa[mt][1], fa[mt][2], fa[mt][3], aB + aoff);
            }
            #pragma unroll
            for (int p = 0; p < 2; p++) {
                uint32_t boff = SWZ128((uint32_t)((bRowSel + p * 16) * 128 + kk * 32 + bByteSel));
                LDSM_X4(fb[p][0], fb[p][1], fb[p][2], fb[p][3], bB + boff);
            }
            #pragma unroll
            for (int mt = 0; mt < 4; mt++)
                #pragma unroll
                for (int nt = 0; nt < 4; nt++)
                    MMA16816(acc[mt][nt],
                             fa[mt][0], fa[mt][1], fa[mt][2], fa[mt][3],
                             fb[nt >> 1][(nt & 1) * 2], fb[nt >> 1][(nt & 1) * 2 + 1]);
        }
    }

    // epilogue: bias + store
    #pragma unroll
    for (int mt = 0; mt < 4; mt++) {
        int r0 = m0 + warpM * 64 + mt * 16 + (lane >> 2);
        #pragma unroll
        for (int nt = 0; nt < 4; nt++) {
            int c0 = n0 + warpN * 32 + nt * 8 + (lane & 3) * 2;
            float2 bv = *(const float2*)(bias + c0);
            float2 o0 = make_float2(acc[mt][nt][0] + bv.x, acc[mt][nt][1] + bv.y);
            float2 o1 = make_float2(acc[mt][nt][2] + bv.x, acc[mt][nt][3] + bv.y);
            *(float2*)(C + (size_t)r0 * N + c0)       = o0;
            *(float2*)(C + (size_t)(r0 + 8) * N + c0) = o1;
        }
    }
}

// ---------------------------------------------------------------------------
// Convert fp32 -> fp16
// ---------------------------------------------------------------------------
__global__ __launch_bounds__(256)
void conv_fp16_kernel(const float* __restrict__ in,
                      __half* __restrict__ o, int n4)
{
    int i = blockIdx.x * 256 + threadIdx.x;
    if (i >= n4) return;
    float4 v = ((const float4*)in)[i];
    ((__half2*)o)[2 * i + 0] = __halves2half2(__float2half_rn(v.x), __float2half_rn(v.y));
    ((__half2*)o)[2 * i + 1] = __halves2half2(__float2half_rn(v.z), __float2half_rn(v.w));
}

// ---------------------------------------------------------------------------
// Transpose: W[K,N] fp32 -> Wt[N,K] fp16
// ---------------------------------------------------------------------------
__global__ __launch_bounds__(256)
void conv_transpose_kernel(const float* __restrict__ W,
                           __half* __restrict__ o, int K, int N)
{
    __shared__ float tile[32][33];
    const int n0 = blockIdx.x * 32;
    const int k0 = blockIdx.y * 32;
    const int tx = threadIdx.x & 31;
    const int ty = threadIdx.x >> 5;

    #pragma unroll
    for (int j = ty; j < 32; j += 8)
        tile[j][tx] = W[(size_t)(k0 + j) * N + n0 + tx];
    __syncthreads();

    #pragma unroll
    for (int j = ty; j < 32; j += 8)
        o[(size_t)(n0 + j) * K + k0 + tx] = __float2half_rn(tile[tx][j]);
}

// ---------------------------------------------------------------------------
// Fenwick sparse attention — parallel-position formulation (verified R8-R11).
// Q,K,V all fp32 from qkv (R11 exact). fp16 output feeds GEMM2 A operand.
// ---------------------------------------------------------------------------
__global__ __launch_bounds__(256)
void fenwick_attn_kernel(const float* __restrict__ qkv,
                         __half* __restrict__ outA)
{
    const int warp = threadIdx.x >> 5;
    const int lane = threadIdx.x & 31;
    const int t  = blockIdx.x * 8 + warp;
    const int bh = blockIdx.y;
    const int b = bh >> 4;
    const int h = bh & 15;

    const float scale = 0.125f;
    const size_t rowStride = 3 * CH;
    const float* base = qkv + (size_t)b * SEQ * rowStride;

    bool active;
    int myPos;
    if (lane == 0) { myPos = t; active = true; }
    else           { int step = 1 << (lane - 1);
                     myPos = t - step;
                     active = (lane < 12) && (myPos >= 0); }
    if (!active) myPos = t;

    float s = -CUDART_INF_F;
    if (active) {
        const float4* qp4 = (const float4*)(base + (size_t)t * rowStride + h * DH);
        const float4* kp4 = (const float4*)(base + (size_t)myPos * rowStride + CH + h * DH);
        float d = 0.0f;
        #pragma unroll
        for (int i = 0; i < 16; i++) {
            float4 qv = qp4[i];
            float4 kv = kp4[i];
            d += qv.x * kv.x + qv.y * kv.y + qv.z * kv.z + qv.w * kv.w;
        }
        s = d * scale;
    }

    float m = s;
    #pragma unroll
    for (int off = 16; off; off >>= 1) m = fmaxf(m, __shfl_xor_sync(0xFFFFFFFFu, m, off));
    float e = active ? __expf(s - m) : 0.0f;
    float denom = e;
    #pragma unroll
    for (int off = 16; off; off >>= 1) denom += __shfl_xor_sync(0xFFFFFFFFu, denom, off);
    const float inv = 1.0f / denom;

    float o0 = 0.0f, o1 = 0.0f;
    #pragma unroll
    for (int j = 0; j < 12; j++) {
        float ej = __shfl_sync(0xFFFFFFFFu, e, j);
        int   pj = __shfl_sync(0xFFFFFFFFu, myPos, j);
        const float* vp = base + (size_t)pj * rowStride + 2 * CH + h * DH;
        o0 = fmaf(ej, vp[lane], o0);
        o1 = fmaf(ej, vp[lane + 32], o1);
    }
    o0 *= inv;
    o1 *= inv;

    const size_t o = ((size_t)b * SEQ + t) * CH + h * DH;
    outA[o + lane]      = __float2half_rn(o0);
    outA[o + lane + 32] = __float2half_rn(o1);
}

// ---------------------------------------------------------------------------
// Launch
// ---------------------------------------------------------------------------
extern "C" void kernel_launch(void* const* d_in, const int* in_sizes, int n_in,
                              void* d_out, int out_size)
{
    const float* x      = (const float*)d_in[0];
    const float* W_qkv  = (const float*)d_in[1];
    const float* b_qkv  = (const float*)d_in[2];
    const float* W_proj = (const float*)d_in[3];
    const float* b_proj = (const float*)d_in[4];
    float* out = (float*)d_out;

    float *qkv;
    __half *A, *BQ, *BP;
    cudaGetSymbolAddress((void**)&qkv, g_qkv);
    cudaGetSymbolAddress((void**)&A,   g_A);
    cudaGetSymbolAddress((void**)&BQ,  g_BQ);
    cudaGetSymbolAddress((void**)&BP,  g_BP);

    cudaFuncSetAttribute(gemm_fp16_kernel,
                         cudaFuncAttributeMaxDynamicSharedMemorySize, GEMM_SMEM);

    conv_transpose_kernel<<<dim3(3 * CH / 32, CH / 32), 256>>>(W_qkv, BQ, CH, 3 * CH);
    conv_transpose_kernel<<<dim3(CH / 32, CH / 32), 256>>>(W_proj, BP, CH, CH);
    conv_fp16_kernel<<<(MROWS * CH / 4 + 255) / 256, 256>>>(x, A, MROWS * CH / 4);

    // GEMM1: [4096, 3072] = x @ W_qkv + b_qkv
    gemm_fp16_kernel<<<dim3(3 * CH / 128, MROWS / 128), 256, GEMM_SMEM>>>(
        A, BQ, b_qkv, qkv, 3 * CH, CH);

    // Attention, fp16 output (overwrites A)
    fenwick_attn_kernel<<<dim3(SEQ / 8, BATCH * HEADS), 256>>>(qkv, A);

    // GEMM2: [4096, 1024] = att @ W_proj + b_proj
    gemm_fp16_kernel<<<dim3(CH / 128, MROWS / 128), 256, GEMM_SMEM>>>(
        A, BP, b_proj, out, CH, CH);
}